// round 11
// baseline (speedup 1.0000x reference)
#include <cuda_runtime.h>

#define BLK  128
#define ROW  73            // odd stride: per-thread compute rows conflict-free
#define TILE 128           // elements per tile (= BLK, one element/thread)
#define BUFW (BLK * ROW)   // words per buffer
#define NCTA 444           // 3 CTAs/SM x 148 SMs: whole grid resident, 1 wave

__constant__ float JC[24 * 16];   // rest-pose J (offsets at [j*16+{3,7,11}])

// ---- cp.async 4B: global -> shared without register round-trip ------------
__device__ __forceinline__ void cp4(unsigned sdst, const float* src) {
    asm volatile("cp.async.ca.shared.global [%0], [%1], 4;"
                 :: "r"(sdst), "l"(src));
}
__device__ __forceinline__ void cp_commit() {
    asm volatile("cp.async.commit_group;");
}
__device__ __forceinline__ void cp_wait_all() {
    asm volatile("cp.async.wait_group 0;");
}

// ---- Rodrigues (no sqrt/sin/cos; degree-4 Taylor in u = |r|^2) -------------
__device__ __forceinline__ float polyA(float u) {
    float A = fmaf(u,  2.75573192e-6f, -1.98412698e-4f);
    A = fmaf(A, u,  8.33333333e-3f);
    A = fmaf(A, u, -1.66666667e-1f);
    return fmaf(A, u, 1.0f);
}
__device__ __forceinline__ float polyB(float u) {
    float Bv = fmaf(u,  2.75573192e-7f, -2.48015873e-5f);
    Bv = fmaf(Bv, u,  1.38888889e-3f);
    Bv = fmaf(Bv, u, -4.16666667e-2f);
    return fmaf(Bv, u, 0.5f);
}
__device__ __forceinline__ void rodr3(float x, float y, float z, float R[9]) {
    const float u = fmaf(x, x, fmaf(y, y, z * z));
    const float A = polyA(u), Bv = polyB(u);
    const float c = fmaf(-Bv, u, 1.0f);
    const float Bx = Bv * x, By = Bv * y, Bz = Bv * z;
    const float Ax = A * x,  Ay = A * y,  Az = A * z;
    const float Bxy = Bx * y, Bxz = Bx * z, Byz = By * z;
    R[0] = fmaf(Bx, x, c);  R[4] = fmaf(By, y, c);  R[8] = fmaf(Bz, z, c);
    R[1] = Bxy - Az;  R[3] = Bxy + Az;
    R[2] = Bxz + Ay;  R[6] = Bxz - Ay;
    R[5] = Byz - Ax;  R[7] = Byz + Ax;
}

// Non-leaf child J: t' = G*off + t ; emit ; G' = G * R(pose_J).
template <int J>
__device__ __forceinline__ void stepNL(float G[9], float t[3],
                                       float* __restrict__ mp) {
    const float ox = JC[J*16+3], oy = JC[J*16+7], oz = JC[J*16+11];
    const float n0 = fmaf(G[0], ox, fmaf(G[1], oy, fmaf(G[2], oz, t[0])));
    const float n1 = fmaf(G[3], ox, fmaf(G[4], oy, fmaf(G[5], oz, t[1])));
    const float n2 = fmaf(G[6], ox, fmaf(G[7], oy, fmaf(G[8], oz, t[2])));
    float R[9];
    rodr3(mp[J*3+0], mp[J*3+1], mp[J*3+2], R);
#pragma unroll
    for (int r = 0; r < 3; r++) {
        const float g0 = G[r*3+0], g1 = G[r*3+1], g2 = G[r*3+2];
        G[r*3+0] = fmaf(g0, R[0], fmaf(g1, R[3], g2 * R[6]));
        G[r*3+1] = fmaf(g0, R[1], fmaf(g1, R[4], g2 * R[7]));
        G[r*3+2] = fmaf(g0, R[2], fmaf(g1, R[5], g2 * R[8]));
    }
    t[0] = n0; t[1] = n1; t[2] = n2;
    mp[J*3+0] = n0; mp[J*3+1] = n1; mp[J*3+2] = n2;
}
template <int J>
__device__ __forceinline__ void stepLeaf(const float G[9], const float t[3],
                                         float* __restrict__ mp) {
    const float ox = JC[J*16+3], oy = JC[J*16+7], oz = JC[J*16+11];
    mp[J*3+0] = fmaf(G[0], ox, fmaf(G[1], oy, fmaf(G[2], oz, t[0])));
    mp[J*3+1] = fmaf(G[3], ox, fmaf(G[4], oy, fmaf(G[5], oz, t[1])));
    mp[J*3+2] = fmaf(G[6], ox, fmaf(G[7], oy, fmaf(G[8], oz, t[2])));
}

// Full scalar tree walk on one staged row (R9-proven, ~80 regs).
__device__ __forceinline__ void walk(float* __restrict__ mp,
                                     float tr0, float tr1, float tr2) {
    float G[9], t[3], Gs[9], ts[3];
    rodr3(mp[0], mp[1], mp[2], G);
    t[0] = JC[3]  + tr0;  t[1] = JC[7]  + tr1;  t[2] = JC[11] + tr2;
    mp[0] = t[0]; mp[1] = t[1]; mp[2] = t[2];
#pragma unroll
    for (int i = 0; i < 9; i++) Gs[i] = G[i];
    ts[0] = t[0]; ts[1] = t[1]; ts[2] = t[2];

    stepNL<1>(G, t, mp);  stepNL<4>(G, t, mp);  stepNL<7>(G, t, mp);
    stepLeaf<10>(G, t, mp);

#pragma unroll
    for (int i = 0; i < 9; i++) G[i] = Gs[i];
    t[0] = ts[0]; t[1] = ts[1]; t[2] = ts[2];
    stepNL<2>(G, t, mp);  stepNL<5>(G, t, mp);  stepNL<8>(G, t, mp);
    stepLeaf<11>(G, t, mp);

#pragma unroll
    for (int i = 0; i < 9; i++) G[i] = Gs[i];
    t[0] = ts[0]; t[1] = ts[1]; t[2] = ts[2];
    stepNL<3>(G, t, mp);  stepNL<6>(G, t, mp);  stepNL<9>(G, t, mp);
#pragma unroll
    for (int i = 0; i < 9; i++) Gs[i] = G[i];
    ts[0] = t[0]; ts[1] = t[1]; ts[2] = t[2];

    stepNL<12>(G, t, mp); stepLeaf<15>(G, t, mp);

#pragma unroll
    for (int i = 0; i < 9; i++) G[i] = Gs[i];
    t[0] = ts[0]; t[1] = ts[1]; t[2] = ts[2];
    stepNL<13>(G, t, mp); stepNL<16>(G, t, mp); stepNL<18>(G, t, mp);
    stepNL<20>(G, t, mp); stepLeaf<22>(G, t, mp);

    stepNL<14>(Gs, ts, mp); stepNL<17>(Gs, ts, mp); stepNL<19>(Gs, ts, mp);
    stepNL<21>(Gs, ts, mp); stepLeaf<23>(Gs, ts, mp);
}

__global__ void __launch_bounds__(BLK, 3)
skel_kernel(const float* __restrict__ pose,
            const float* __restrict__ trans,
            float* __restrict__ out, int B, int NT) {
    extern __shared__ float s[];            // 2 buffers x BUFW words

    const int tid  = threadIdx.x;
    const int lane = tid & 31;
    const int wrp  = tid >> 5;

    // Word-granular conflict-free transpose bases (R8-proven):
    // global word v = lane+32k -> smem word v + v/72; period 9 phases.
    int base[9];
    {
        int bb = 0, cc = lane;
#pragma unroll
        for (int p = 0; p < 9; p++) {
            base[p] = 73 * bb + cc;
            cc += 32;
            if (cc >= 72) { cc -= 72; bb++; }
        }
    }

    // Shared-space byte addresses of this warp's two buffers.
    const unsigned sw0 = (unsigned)__cvta_generic_to_shared(s + wrp * 32 * ROW);
    const unsigned sw1 = (unsigned)__cvta_generic_to_shared(s + BUFW + wrp * 32 * ROW);

    // ---- stage(tile -> buffer) via cp.async (no regs, no STS) ------------
    auto stage = [&](int tile, unsigned swu) {
        const int wb0 = tile * TILE + wrp * 32;
        const float* gw = pose + (long long)wb0 * 72;
        if (wb0 + 32 <= B) {
#pragma unroll
            for (int j = 0; j < 8; j++)
#pragma unroll
                for (int p = 0; p < 9; p++)
                    cp4(swu + 4u * (base[p] + 292 * j),
                        gw + (lane + 32 * p + 288 * j));
        } else {
#pragma unroll
            for (int j = 0; j < 8; j++)
#pragma unroll
                for (int p = 0; p < 9; p++) {
                    const int v = lane + 32 * p + 288 * j;
                    if (wb0 + v / 72 < B)
                        cp4(swu + 4u * (base[p] + 292 * j), gw + v);
                }
        }
        cp_commit();
    };

    // ---- drain(buffer -> out[tile]) ---------------------------------------
    auto drain = [&](int tile, const float* sw) {
        const int wb0 = tile * TILE + wrp * 32;
        float* go = out + (long long)wb0 * 72;
        if (wb0 + 32 <= B) {
#pragma unroll
            for (int j = 0; j < 8; j++)
#pragma unroll
                for (int p = 0; p < 9; p++)
                    go[lane + 32 * p + 288 * j] = sw[base[p] + 292 * j];
        } else {
#pragma unroll
            for (int j = 0; j < 8; j++)
#pragma unroll
                for (int p = 0; p < 9; p++) {
                    const int v = lane + 32 * p + 288 * j;
                    if (wb0 + v / 72 < B)
                        go[v] = sw[base[p] + 292 * j];
                }
        }
    };

    // ---- software pipeline over grid-strided tiles -------------------------
    int tile = blockIdx.x;
    if (tile >= NT) return;
    int cur = 0;

    // Prime: stage tile0 + its trans.
    stage(tile, sw0);
    float tr0 = 0.f, tr1 = 0.f, tr2 = 0.f;
    {
        const int myb = tile * TILE + tid;
        if (myb < B) { tr0 = trans[myb*3+0]; tr1 = trans[myb*3+1]; tr2 = trans[myb*3+2]; }
    }
    cp_wait_all();
    __syncwarp();

    for (;;) {
        const int next = tile + gridDim.x;
        const bool more = (next < NT);

        // Issue next tile's async stage + trans load NOW; they complete
        // under the ~12K cycles of compute+drain below.
        float nr0 = 0.f, nr1 = 0.f, nr2 = 0.f;
        if (more) {
            stage(next, cur ? sw0 : sw1);
            const int nb = next * TILE + tid;
            if (nb < B) { nr0 = trans[nb*3+0]; nr1 = trans[nb*3+1]; nr2 = trans[nb*3+2]; }
        }

        // Compute current tile in place (results overwrite pose rows).
        float* bufc = s + (cur ? BUFW : 0);
        {
            const int myb = tile * TILE + tid;
            if (myb < B) walk(bufc + tid * ROW, tr0, tr1, tr2);
        }
        __syncwarp();            // drain reads other lanes' rows
        drain(tile, bufc + wrp * 32 * ROW);

        if (!more) break;
        cp_wait_all();           // next tile's data has landed
        __syncwarp();            // all lanes past drain before buffer reuse
        tile = next; cur ^= 1;
        tr0 = nr0; tr1 = nr1; tr2 = nr2;
    }
}

extern "C" void kernel_launch(void* const* d_in, const int* in_sizes, int n_in,
                              void* d_out, int out_size) {
    // Identify inputs by element count (expected order: pose, trans, J, parents)
    int ip = 0;
    long long mx = -1;
    for (int i = 0; i < n_in; i++)
        if ((long long)in_sizes[i] > mx) { mx = in_sizes[i]; ip = i; }
    const int B = in_sizes[ip] / 72;            // pose: [B,24,3]

    int it = -1, ij = -1;
    for (int i = 0; i < n_in; i++) {
        if (i == ip) continue;
        if (in_sizes[i] == B * 3) it = i;        // trans: [B,3]
        else if (in_sizes[i] == 24 * 16) ij = i; // J: [24,4,4]
    }
    if (it < 0) it = 1;
    if (ij < 0) ij = 2;

    // J -> constant memory (device-to-device async; graph-capturable).
    cudaMemcpyToSymbolAsync(JC, d_in[ij], 24 * 16 * sizeof(float), 0,
                            cudaMemcpyDeviceToDevice, 0);

    const int smem = 2 * BUFW * sizeof(float);   // 74.75 KB: 3 CTAs/SM
    cudaFuncSetAttribute(skel_kernel,
                         cudaFuncAttributeMaxDynamicSharedMemorySize, smem);
    cudaFuncSetAttribute(skel_kernel,
                         cudaFuncAttributePreferredSharedMemoryCarveout, 100);

    const int NT = (B + TILE - 1) / TILE;
    const int grid = NT < NCTA ? NT : NCTA;
    skel_kernel<<<grid, BLK, smem>>>((const float*)d_in[ip],
                                     (const float*)d_in[it],
                                     (float*)d_out, B, NT);
}

// round 12
// speedup vs baseline: 1.0931x; 1.0931x over previous
#include <cuda_runtime.h>

#define BLK 128
#define ROW 100   // padded rows: joint j at words 4j..4j+2 -> LDS.128/STS.128
                  // lane stride 100 = 4 mod 32: vector ops conflict-free

__constant__ float JC[24 * 16];   // rest-pose J (offsets at [j*16+{3,7,11}])

// ---- Rodrigues (no sqrt/sin/cos; degree-4 Taylor in u = |r|^2) -------------
__device__ __forceinline__ float polyA(float u) {
    float A = fmaf(u,  2.75573192e-6f, -1.98412698e-4f);
    A = fmaf(A, u,  8.33333333e-3f);
    A = fmaf(A, u, -1.66666667e-1f);
    return fmaf(A, u, 1.0f);
}
__device__ __forceinline__ float polyB(float u) {
    float Bv = fmaf(u,  2.75573192e-7f, -2.48015873e-5f);
    Bv = fmaf(Bv, u,  1.38888889e-3f);
    Bv = fmaf(Bv, u, -4.16666667e-2f);
    return fmaf(Bv, u, 0.5f);
}
__device__ __forceinline__ void rodr3(float x, float y, float z, float R[9]) {
    const float u = fmaf(x, x, fmaf(y, y, z * z));
    const float A = polyA(u), Bv = polyB(u);
    const float c = fmaf(-Bv, u, 1.0f);
    const float Bx = Bv * x, By = Bv * y, Bz = Bv * z;
    const float Ax = A * x,  Ay = A * y,  Az = A * z;
    const float Bxy = Bx * y, Bxz = Bx * z, Byz = By * z;
    R[0] = fmaf(Bx, x, c);  R[4] = fmaf(By, y, c);  R[8] = fmaf(Bz, z, c);
    R[1] = Bxy - Az;  R[3] = Bxy + Az;
    R[2] = Bxz + Ay;  R[6] = Bxz - Ay;
    R[5] = Byz - Ax;  R[7] = Byz + Ax;
}

// Pose slot J as one LDS.128 (16B-aligned: tid*400B + 16J B).
template <int J>
__device__ __forceinline__ float4 ldp(const float* __restrict__ mp) {
    return *reinterpret_cast<const float4*>(mp + 4 * J);
}

// Non-leaf joint J with PRELOADED pose p: t' = G*off + t (STS.128); G' = G*R(p).
template <int J>
__device__ __forceinline__ void stepNL(float G[9], float t[3],
                                       float* __restrict__ mp, float4 p) {
    const float ox = JC[J*16+3], oy = JC[J*16+7], oz = JC[J*16+11];
    const float n0 = fmaf(G[0], ox, fmaf(G[1], oy, fmaf(G[2], oz, t[0])));
    const float n1 = fmaf(G[3], ox, fmaf(G[4], oy, fmaf(G[5], oz, t[1])));
    const float n2 = fmaf(G[6], ox, fmaf(G[7], oy, fmaf(G[8], oz, t[2])));
    float R[9];
    rodr3(p.x, p.y, p.z, R);
#pragma unroll
    for (int r = 0; r < 3; r++) {
        const float g0 = G[r*3+0], g1 = G[r*3+1], g2 = G[r*3+2];
        G[r*3+0] = fmaf(g0, R[0], fmaf(g1, R[3], g2 * R[6]));
        G[r*3+1] = fmaf(g0, R[1], fmaf(g1, R[4], g2 * R[7]));
        G[r*3+2] = fmaf(g0, R[2], fmaf(g1, R[5], g2 * R[8]));
    }
    t[0] = n0; t[1] = n1; t[2] = n2;
    *reinterpret_cast<float4*>(mp + 4 * J) = make_float4(n0, n1, n2, n2);
}
// Leaf joint J: position only (one STS.128; pad word unused).
template <int J>
__device__ __forceinline__ void stepLeaf(const float G[9], const float t[3],
                                         float* __restrict__ mp) {
    const float ox = JC[J*16+3], oy = JC[J*16+7], oz = JC[J*16+11];
    const float n0 = fmaf(G[0], ox, fmaf(G[1], oy, fmaf(G[2], oz, t[0])));
    const float n1 = fmaf(G[3], ox, fmaf(G[4], oy, fmaf(G[5], oz, t[1])));
    const float n2 = fmaf(G[6], ox, fmaf(G[7], oy, fmaf(G[8], oz, t[2])));
    *reinterpret_cast<float4*>(mp + 4 * J) = make_float4(n0, n1, n2, n2);
}

__global__ void __launch_bounds__(BLK, 4)
skel_kernel(const float* __restrict__ pose,
            const float* __restrict__ trans,
            float* __restrict__ out, int B) {
    extern __shared__ float s[];   // BLK * ROW words (51.2 KB)

    const int tid  = threadIdx.x;
    const int lane = tid & 31;
    const int wrp  = tid >> 5;
    const int b0   = blockIdx.x * BLK;
    const int wb0  = b0 + wrp * 32;
    const int myb  = b0 + tid;
    const bool inb = (myb < B);

    // Hoisted trans loads (consumed much later; latency hidden).
    float tr0 = 0.f, tr1 = 0.f, tr2 = 0.f;
    if (inb) { tr0 = trans[myb*3+0]; tr1 = trans[myb*3+1]; tr2 = trans[myb*3+2]; }

    // --- Transpose bases: global word v = lane+32k -> smem word
    //     100*(v/72) + slot(v%72), slot(w) = w + w/3 (pad-4 joint slots).
    //     Period 9 phases; per-j increments +400 smem / +288 global.
    int sbase[9];
    {
        int bb = 0, cc = lane;
#pragma unroll
        for (int p = 0; p < 9; p++) {
            sbase[p] = 100 * bb + cc + cc / 3;
            cc += 32;
            if (cc >= 72) { cc -= 72; bb++; }
        }
    }

    // --- Stage: coalesced scalar LDG -> slot-mapped STS (<=2-way conflicts).
    // Warp-autonomous; no block barrier anywhere.
    const float* gw = pose + (long long)wb0 * 72;
    float* sw = s + wrp * 32 * ROW;
    if (wb0 + 32 <= B) {
#pragma unroll
        for (int j = 0; j < 8; j++)
#pragma unroll
            for (int p = 0; p < 9; p++)
                sw[sbase[p] + 400 * j] = gw[lane + 32 * p + 288 * j];
    } else {
#pragma unroll
        for (int j = 0; j < 8; j++)
#pragma unroll
            for (int p = 0; p < 9; p++) {
                const int v = lane + 32 * p + 288 * j;
                if (wb0 + v / 72 < B)
                    sw[sbase[p] + 400 * j] = gw[v];
            }
    }
    __syncwarp();   // this warp's rows staged

    // --- Scalar tree walk, one-ahead pose prefetch (LDS.128 per joint) -----
    if (inb) {
        float* mp = &s[tid * ROW];
        float G[9], t[3], Gs[9], ts[3];
        float4 p, q;

        p = ldp<0>(mp);
        q = ldp<1>(mp);                    // prefetch joint 1
        rodr3(p.x, p.y, p.z, G);
        t[0] = JC[3]  + tr0;  t[1] = JC[7]  + tr1;  t[2] = JC[11] + tr2;
        *reinterpret_cast<float4*>(mp) = make_float4(t[0], t[1], t[2], t[2]);

#pragma unroll
        for (int i = 0; i < 9; i++) Gs[i] = G[i];
        ts[0] = t[0]; ts[1] = t[1]; ts[2] = t[2];

        // Left leg 1->4->7->10L (prefetch runs one joint ahead, crossing chains)
        p = q; q = ldp<4>(mp);   stepNL<1>(G, t, mp, p);
        p = q; q = ldp<7>(mp);   stepNL<4>(G, t, mp, p);
        p = q; q = ldp<2>(mp);   stepNL<7>(G, t, mp, p);
        stepLeaf<10>(G, t, mp);

        // Right leg 2->5->8->11L
#pragma unroll
        for (int i = 0; i < 9; i++) G[i] = Gs[i];
        t[0] = ts[0]; t[1] = ts[1]; t[2] = ts[2];
        p = q; q = ldp<5>(mp);   stepNL<2>(G, t, mp, p);
        p = q; q = ldp<8>(mp);   stepNL<5>(G, t, mp, p);
        p = q; q = ldp<3>(mp);   stepNL<8>(G, t, mp, p);
        stepLeaf<11>(G, t, mp);

        // Spine 3->6->9 (branch), head 12->15L
#pragma unroll
        for (int i = 0; i < 9; i++) G[i] = Gs[i];
        t[0] = ts[0]; t[1] = ts[1]; t[2] = ts[2];
        p = q; q = ldp<6>(mp);   stepNL<3>(G, t, mp, p);
        p = q; q = ldp<9>(mp);   stepNL<6>(G, t, mp, p);
        p = q; q = ldp<12>(mp);  stepNL<9>(G, t, mp, p);
#pragma unroll
        for (int i = 0; i < 9; i++) Gs[i] = G[i];
        ts[0] = t[0]; ts[1] = t[1]; ts[2] = t[2];
        p = q; q = ldp<13>(mp);  stepNL<12>(G, t, mp, p);
        stepLeaf<15>(G, t, mp);

        // Left arm 13->16->18->20->22L
#pragma unroll
        for (int i = 0; i < 9; i++) G[i] = Gs[i];
        t[0] = ts[0]; t[1] = ts[1]; t[2] = ts[2];
        p = q; q = ldp<16>(mp);  stepNL<13>(G, t, mp, p);
        p = q; q = ldp<18>(mp);  stepNL<16>(G, t, mp, p);
        p = q; q = ldp<20>(mp);  stepNL<18>(G, t, mp, p);
        p = q; q = ldp<14>(mp);  stepNL<20>(G, t, mp, p);
        stepLeaf<22>(G, t, mp);

        // Right arm 14->17->19->21->23L (consumes Gs in place)
        p = q; q = ldp<17>(mp);  stepNL<14>(Gs, ts, mp, p);
        p = q; q = ldp<19>(mp);  stepNL<17>(Gs, ts, mp, p);
        p = q; q = ldp<21>(mp);  stepNL<19>(Gs, ts, mp, p);
        p = q;                   stepNL<21>(Gs, ts, mp, p);
        stepLeaf<23>(Gs, ts, mp);
    }
    __syncwarp();   // drain reads only this warp's rows

    // --- Drain: slot-mapped scalar LDS -> coalesced scalar STG -------------
    float* go = out + (long long)wb0 * 72;
    if (wb0 + 32 <= B) {
#pragma unroll
        for (int j = 0; j < 8; j++)
#pragma unroll
            for (int p = 0; p < 9; p++)
                go[lane + 32 * p + 288 * j] = sw[sbase[p] + 400 * j];
    } else {
#pragma unroll
        for (int j = 0; j < 8; j++)
#pragma unroll
            for (int p = 0; p < 9; p++) {
                const int v = lane + 32 * p + 288 * j;
                if (wb0 + v / 72 < B)
                    go[v] = sw[sbase[p] + 400 * j];
            }
    }
}

extern "C" void kernel_launch(void* const* d_in, const int* in_sizes, int n_in,
                              void* d_out, int out_size) {
    // Identify inputs by element count (expected order: pose, trans, J, parents)
    int ip = 0;
    long long mx = -1;
    for (int i = 0; i < n_in; i++)
        if ((long long)in_sizes[i] > mx) { mx = in_sizes[i]; ip = i; }
    const int B = in_sizes[ip] / 72;            // pose: [B,24,3]

    int it = -1, ij = -1;
    for (int i = 0; i < n_in; i++) {
        if (i == ip) continue;
        if (in_sizes[i] == B * 3) it = i;        // trans: [B,3]
        else if (in_sizes[i] == 24 * 16) ij = i; // J: [24,4,4]
    }
    if (it < 0) it = 1;
    if (ij < 0) ij = 2;

    // J -> constant memory (device-to-device async; graph-capturable).
    cudaMemcpyToSymbolAsync(JC, d_in[ij], 24 * 16 * sizeof(float), 0,
                            cudaMemcpyDeviceToDevice, 0);

    const int smem = BLK * ROW * sizeof(float);   // 51.2 KB -> 4 CTAs/SM
    cudaFuncSetAttribute(skel_kernel,
                         cudaFuncAttributeMaxDynamicSharedMemorySize, smem);
    cudaFuncSetAttribute(skel_kernel,
                         cudaFuncAttributePreferredSharedMemoryCarveout, 100);

    const int grid = (B + BLK - 1) / BLK;
    skel_kernel<<<grid, BLK, smem>>>((const float*)d_in[ip],
                                     (const float*)d_in[it],
                                     (float*)d_out, B);
}

// round 13
// speedup vs baseline: 1.2052x; 1.1026x over previous
#include <cuda_runtime.h>

#define BLK 128
#define ROW 73   // odd row stride: per-thread compute rows hit distinct banks

// ---- Rodrigues (no sqrt/sin/cos; degree-4 Taylor in u = |r|^2) -------------
__device__ __forceinline__ float polyA(float u) {
    float A = fmaf(u,  2.75573192e-6f, -1.98412698e-4f);
    A = fmaf(A, u,  8.33333333e-3f);
    A = fmaf(A, u, -1.66666667e-1f);
    return fmaf(A, u, 1.0f);
}
__device__ __forceinline__ float polyB(float u) {
    float Bv = fmaf(u,  2.75573192e-7f, -2.48015873e-5f);
    Bv = fmaf(Bv, u,  1.38888889e-3f);
    Bv = fmaf(Bv, u, -4.16666667e-2f);
    return fmaf(Bv, u, 0.5f);
}
__device__ __forceinline__ void rodr3(float x, float y, float z, float R[9]) {
    const float u = fmaf(x, x, fmaf(y, y, z * z));
    const float A = polyA(u), Bv = polyB(u);
    const float c = fmaf(-Bv, u, 1.0f);
    const float Bx = Bv * x, By = Bv * y, Bz = Bv * z;
    const float Ax = A * x,  Ay = A * y,  Az = A * z;
    const float Bxy = Bx * y, Bxz = Bx * z, Byz = By * z;
    R[0] = fmaf(Bx, x, c);  R[4] = fmaf(By, y, c);  R[8] = fmaf(Bz, z, c);
    R[1] = Bxy - Az;  R[3] = Bxy + Az;
    R[2] = Bxz + Ay;  R[6] = Bxz - Ay;
    R[5] = Byz - Ax;  R[7] = Byz + Ax;
}

// Non-leaf child J: t' = G*off + t ; emit ; G' = G * R(pose_J).
// Offset = ONE broadcast LDS.128 from the per-CTA table (uniform address).
template <int J>
__device__ __forceinline__ void stepNL(float G[9], float t[3],
                                       float* __restrict__ mp,
                                       const float4* __restrict__ off) {
    const float4 o = off[J];
    const float n0 = fmaf(G[0], o.x, fmaf(G[1], o.y, fmaf(G[2], o.z, t[0])));
    const float n1 = fmaf(G[3], o.x, fmaf(G[4], o.y, fmaf(G[5], o.z, t[1])));
    const float n2 = fmaf(G[6], o.x, fmaf(G[7], o.y, fmaf(G[8], o.z, t[2])));

    float R[9];
    rodr3(mp[J*3+0], mp[J*3+1], mp[J*3+2], R);   // read pose before overwrite

#pragma unroll
    for (int r = 0; r < 3; r++) {
        const float g0 = G[r*3+0], g1 = G[r*3+1], g2 = G[r*3+2];
        G[r*3+0] = fmaf(g0, R[0], fmaf(g1, R[3], g2 * R[6]));
        G[r*3+1] = fmaf(g0, R[1], fmaf(g1, R[4], g2 * R[7]));
        G[r*3+2] = fmaf(g0, R[2], fmaf(g1, R[5], g2 * R[8]));
    }
    t[0] = n0; t[1] = n1; t[2] = n2;
    mp[J*3+0] = n0; mp[J*3+1] = n1; mp[J*3+2] = n2;
}
// Leaf child J: position only.
template <int J>
__device__ __forceinline__ void stepLeaf(const float G[9], const float t[3],
                                         float* __restrict__ mp,
                                         const float4* __restrict__ off) {
    const float4 o = off[J];
    mp[J*3+0] = fmaf(G[0], o.x, fmaf(G[1], o.y, fmaf(G[2], o.z, t[0])));
    mp[J*3+1] = fmaf(G[3], o.x, fmaf(G[4], o.y, fmaf(G[5], o.z, t[1])));
    mp[J*3+2] = fmaf(G[6], o.x, fmaf(G[7], o.y, fmaf(G[8], o.z, t[2])));
}

__global__ void __launch_bounds__(BLK, 6)
skel_kernel(const float* __restrict__ pose,
            const float* __restrict__ trans,
            const float* __restrict__ Jm,
            float* __restrict__ out, int B) {
    __shared__ float  s[BLK * ROW];
    __shared__ float4 offt[24];

    const int tid  = threadIdx.x;
    const int lane = tid & 31;
    const int wrp  = tid >> 5;
    const int b0   = blockIdx.x * BLK;
    const int wb0  = b0 + wrp * 32;
    const int myb  = b0 + tid;
    const bool inb = (myb < B);

    // Per-warp redundant fill of the offset table (benign same-value race;
    // this warp's writes are visible to it after __syncwarp -> NO block
    // barrier anywhere, preserving free warp slip). Replaces the R7-R12
    // cudaMemcpyToSymbol graph node (~0.7us per replay).
    if (lane < 24)
        offt[lane] = make_float4(Jm[lane*16+3], Jm[lane*16+7], Jm[lane*16+11], 0.f);

    // Hoisted trans loads (consumed much later; latency hidden).
    float tr0 = 0.f, tr1 = 0.f, tr2 = 0.f;
    if (inb) { tr0 = trans[myb*3+0]; tr1 = trans[myb*3+1]; tr2 = trans[myb*3+2]; }

    // --- Word-granular conflict-free transpose bases (R8-proven) -----------
    // Global word v = lane + 32k -> smem word 73*(v/72) + v%72 = v + (v/72).
    // Period 32*9 = 288 = 4*72: 9 bases cover all k with immediate increments
    // (+292 smem / +288 global per j). Banks (lane + b) mod 32: conflict-free.
    int base[9];
    {
        int bb = 0, cc = lane;
#pragma unroll
        for (int p = 0; p < 9; p++) {
            base[p] = 73 * bb + cc;
            cc += 32;
            if (cc >= 72) { cc -= 72; bb++; }
        }
    }

    // --- Stage: coalesced scalar LDG -> conflict-free scalar STS -----------
    const float* gw = pose + (long long)wb0 * 72;
    float* sw = s + wrp * 32 * ROW;
    if (wb0 + 32 <= B) {
#pragma unroll
        for (int j = 0; j < 8; j++)
#pragma unroll
            for (int p = 0; p < 9; p++)
                sw[base[p] + 292 * j] = gw[lane + 32 * p + 288 * j];
    } else {
#pragma unroll
        for (int j = 0; j < 8; j++)
#pragma unroll
            for (int p = 0; p < 9; p++) {
                const int v = lane + 32 * p + 288 * j;
                if (wb0 + v / 72 < B)
                    sw[base[p] + 292 * j] = gw[v];
            }
    }
    __syncwarp();   // staged rows + offset table visible warp-locally

    // --- Per-thread scalar kinematic tree walk (DFS, 2 saved frames) -------
    if (inb) {
        float* mp = &s[tid * ROW];
        float G[9], t[3], Gs[9], ts[3];

        // Root: G = R(pose_0); t = off_0 + trans (trans folds into root).
        rodr3(mp[0], mp[1], mp[2], G);
        {
            const float4 o0 = offt[0];
            t[0] = o0.x + tr0;  t[1] = o0.y + tr1;  t[2] = o0.z + tr2;
        }
        mp[0] = t[0]; mp[1] = t[1]; mp[2] = t[2];

#pragma unroll
        for (int i = 0; i < 9; i++) Gs[i] = G[i];
        ts[0] = t[0]; ts[1] = t[1]; ts[2] = t[2];

        // Left leg: 1 -> 4 -> 7 -> 10(leaf)
        stepNL<1>(G, t, mp, offt);
        stepNL<4>(G, t, mp, offt);
        stepNL<7>(G, t, mp, offt);
        stepLeaf<10>(G, t, mp, offt);

        // Right leg: 2 -> 5 -> 8 -> 11(leaf)
#pragma unroll
        for (int i = 0; i < 9; i++) G[i] = Gs[i];
        t[0] = ts[0]; t[1] = ts[1]; t[2] = ts[2];
        stepNL<2>(G, t, mp, offt);
        stepNL<5>(G, t, mp, offt);
        stepNL<8>(G, t, mp, offt);
        stepLeaf<11>(G, t, mp, offt);

        // Spine: 3 -> 6 -> 9 (branch point; Gs reused for joint 9)
#pragma unroll
        for (int i = 0; i < 9; i++) G[i] = Gs[i];
        t[0] = ts[0]; t[1] = ts[1]; t[2] = ts[2];
        stepNL<3>(G, t, mp, offt);
        stepNL<6>(G, t, mp, offt);
        stepNL<9>(G, t, mp, offt);
#pragma unroll
        for (int i = 0; i < 9; i++) Gs[i] = G[i];
        ts[0] = t[0]; ts[1] = t[1]; ts[2] = t[2];

        // Head: 12 -> 15(leaf)
        stepNL<12>(G, t, mp, offt);
        stepLeaf<15>(G, t, mp, offt);

        // Left arm: 13 -> 16 -> 18 -> 20 -> 22(leaf)
#pragma unroll
        for (int i = 0; i < 9; i++) G[i] = Gs[i];
        t[0] = ts[0]; t[1] = ts[1]; t[2] = ts[2];
        stepNL<13>(G, t, mp, offt);
        stepNL<16>(G, t, mp, offt);
        stepNL<18>(G, t, mp, offt);
        stepNL<20>(G, t, mp, offt);
        stepLeaf<22>(G, t, mp, offt);

        // Right arm: 14 -> 17 -> 19 -> 21 -> 23(leaf) — consumes Gs in place.
        stepNL<14>(Gs, ts, mp, offt);
        stepNL<17>(Gs, ts, mp, offt);
        stepNL<19>(Gs, ts, mp, offt);
        stepNL<21>(Gs, ts, mp, offt);
        stepLeaf<23>(Gs, ts, mp, offt);
    }
    __syncwarp();   // drain reads only this warp's rows

    // --- Drain: conflict-free scalar LDS -> coalesced scalar STG -----------
    float* go = out + (long long)wb0 * 72;
    if (wb0 + 32 <= B) {
#pragma unroll
        for (int j = 0; j < 8; j++)
#pragma unroll
            for (int p = 0; p < 9; p++)
                go[lane + 32 * p + 288 * j] = sw[base[p] + 292 * j];
    } else {
#pragma unroll
        for (int j = 0; j < 8; j++)
#pragma unroll
            for (int p = 0; p < 9; p++) {
                const int v = lane + 32 * p + 288 * j;
                if (wb0 + v / 72 < B)
                    go[v] = sw[base[p] + 292 * j];
            }
    }
}

extern "C" void kernel_launch(void* const* d_in, const int* in_sizes, int n_in,
                              void* d_out, int out_size) {
    // Identify inputs by element count (expected order: pose, trans, J, parents)
    int ip = 0;
    long long mx = -1;
    for (int i = 0; i < n_in; i++)
        if ((long long)in_sizes[i] > mx) { mx = in_sizes[i]; ip = i; }
    const int B = in_sizes[ip] / 72;            // pose: [B,24,3]

    int it = -1, ij = -1;
    for (int i = 0; i < n_in; i++) {
        if (i == ip) continue;
        if (in_sizes[i] == B * 3) it = i;        // trans: [B,3]
        else if (in_sizes[i] == 24 * 16) ij = i; // J: [24,4,4]
    }
    if (it < 0) it = 1;
    if (ij < 0) ij = 2;

    // Max smem carveout: 6 CTAs x ~37.8KB = 227KB <= 228KB.
    cudaFuncSetAttribute(skel_kernel,
                         cudaFuncAttributePreferredSharedMemoryCarveout, 100);

    const int grid = (B + BLK - 1) / BLK;
    skel_kernel<<<grid, BLK>>>((const float*)d_in[ip],
                               (const float*)d_in[it],
                               (const float*)d_in[ij],
                               (float*)d_out, B);
}